// round 1
// baseline (speedup 1.0000x reference)
#include <cuda_runtime.h>
#include <cuda_bf16.h>
#include <cstdint>

// Problem constants
#define ND      64
#define NP      6
#define SPB     8          // samples per block-tile
#define THREADS 512        // 8 groups x 64 threads

#define W_FLOATS    (3 * 3 * ND * ND)            // 36864 (3 layers, [k][i][o])
#define B_FLOATS    (3 * ND)                     // 192
#define XE_OFF      0
#define XO_OFF      384
#define D1_OFF      768                          // stride-8 padded [64][8]
#define DW_OFF      1280
#define SAMP_FLOATS 1792                         // per-sample staging
#define SMEM_FLOATS (W_FLOATS + B_FLOATS + SPB * SAMP_FLOATS)
#define SMEM_BYTES  (SMEM_FLOATS * 4)            // 205568 B

// ---- packed 2xfp32 helpers (Blackwell f32x2 pipe; 2x FFMA throughput) ----
__device__ __forceinline__ unsigned long long pk2(float lo, float hi) {
    unsigned long long r;
    asm("mov.b64 %0, {%1, %2};" : "=l"(r) : "f"(lo), "f"(hi));
    return r;
}
__device__ __forceinline__ void upk2(unsigned long long v, float& lo, float& hi) {
    asm("mov.b64 {%0, %1}, %2;" : "=f"(lo), "=f"(hi) : "l"(v));
}
__device__ __forceinline__ unsigned long long ffma2(unsigned long long a,
                                                    unsigned long long b,
                                                    unsigned long long c) {
    unsigned long long r;
    asm("fma.rn.f32x2 %0, %1, %2, %3;" : "=l"(r) : "l"(a), "l"(b), "l"(c));
    return r;
}
__device__ __forceinline__ unsigned long long ldp(const float* p) {
    float2 v = *reinterpret_cast<const float2*>(p);
    return pk2(v.x, v.y);
}

__global__ __launch_bounds__(THREADS, 1)
void dijet_resnet_kernel(const float* __restrict__ x,
                         const float* __restrict__ d,
                         const float* __restrict__ W1g, const float* __restrict__ b1g,
                         const float* __restrict__ W2g, const float* __restrict__ b2g,
                         const float* __restrict__ W3g, const float* __restrict__ b3g,
                         float* __restrict__ out, int n) {
    extern __shared__ float sm[];
    float* Wsm  = sm;                  // [3][3][64][64] : layer, k, i, o
    float* bsm  = Wsm + W_FLOATS;      // [3][64]
    float* samp = bsm + B_FLOATS;      // [SPB][SAMP_FLOATS]

    const int tid = threadIdx.x;

    // ---- stage weights (once per persistent block) ----
    {
        const float* Wg[3] = {W1g, W2g, W3g};
        const float* bg[3] = {b1g, b2g, b3g};
#pragma unroll
        for (int l = 0; l < 3; ++l) {
            const float* w = Wg[l];
            for (int idx = tid; idx < ND * ND * 3; idx += THREADS) {
                int o = idx / (ND * 3);
                int r = idx - o * (ND * 3);
                int i = r / 3;
                int k = r - i * 3;
                Wsm[l * (3 * ND * ND) + k * (ND * ND) + i * ND + o] = w[idx];
            }
            if (tid < ND) bsm[l * ND + tid] = bg[l][tid];
        }
    }
    __syncthreads();

    const int group = tid >> 6;    // which of the 8 samples in the tile
    const int o     = tid & 63;    // output channel
    float* xe  = samp + group * SAMP_FLOATS + XE_OFF;   // [64][6] even x
    float* xo  = samp + group * SAMP_FLOATS + XO_OFF;   // [64][6] odd x
    float* d1s = samp + group * SAMP_FLOATS + D1_OFF;   // [64][8] original d
    float* dw  = samp + group * SAMP_FLOATS + DW_OFF;   // [64][8] working d

    const int ntiles = (n + SPB - 1) / SPB;
    for (int tile = blockIdx.x; tile < ntiles; tile += gridDim.x) {
        const int base = tile * SPB;
        const int nact = min(SPB, n - base);

        // ---- stage x (de-interleaved) and d for this tile, coalesced ----
        {
            const float* xg = x + (size_t)base * (ND * 12);
            const int limx = nact * ND * 12;
            for (int idx = tid; idx < limx; idx += THREADS) {
                float v = xg[idx];
                int s_ = idx / (ND * 12);
                int r  = idx - s_ * (ND * 12);
                int i  = r / 12;
                int j  = r - i * 12;
                float* dst = samp + s_ * SAMP_FLOATS + ((j & 1) ? XO_OFF : XE_OFF);
                dst[i * 6 + (j >> 1)] = v;
            }
            const float* dg = d + (size_t)base * (ND * NP);
            const int limd = nact * ND * NP;
            for (int idx = tid; idx < limd; idx += THREADS) {
                float v = dg[idx];
                int s_ = idx / (ND * NP);
                int r  = idx - s_ * (ND * NP);
                int i  = r / NP;
                int ss = r - i * NP;
                samp[s_ * SAMP_FLOATS + D1_OFF + i * 8 + ss] = v;
            }
        }
        __syncthreads();

        const bool active = (base + group) < n;
        unsigned long long a0 = 0, a1 = 0, a2 = 0;

#pragma unroll
        for (int l = 0; l < 3; ++l) {
            const float* Wk0 = Wsm + l * (3 * ND * ND);
            const float* Wk1 = Wk0 + ND * ND;
            const float* Wk2 = Wk1 + ND * ND;
            const float* dsrc = (l == 0) ? d1s : dw;
            const float bb = bsm[l * ND + o];
            a0 = pk2(bb, bb);
            a1 = a0;
            a2 = a0;
#pragma unroll 4
            for (int i = 0; i < ND; ++i) {
                const float w0 = Wk0[i * ND + o];
                const float w1 = Wk1[i * ND + o];
                const float w2 = Wk2[i * ND + o];
                const unsigned long long w0p = pk2(w0, w0);
                const unsigned long long w1p = pk2(w1, w1);
                const unsigned long long w2p = pk2(w2, w2);
                const float* xer = xe + i * 6;
                const float* xor_ = xo + i * 6;
                const float* dr  = dsrc + i * 8;
                a0 = ffma2(ldp(xer + 0), w0p, a0);
                a1 = ffma2(ldp(xer + 2), w0p, a1);
                a2 = ffma2(ldp(xer + 4), w0p, a2);
                a0 = ffma2(ldp(xor_ + 0), w1p, a0);
                a1 = ffma2(ldp(xor_ + 2), w1p, a1);
                a2 = ffma2(ldp(xor_ + 4), w1p, a2);
                a0 = ffma2(ldp(dr + 0), w2p, a0);
                a1 = ffma2(ldp(dr + 2), w2p, a1);
                a2 = ffma2(ldp(dr + 4), w2p, a2);
            }
            if (l < 2) {
                __syncthreads();   // readers of dw/d1s done before we overwrite dw
                float r0, r1, r2, r3, r4, r5;
                upk2(a0, r0, r1);
                upk2(a1, r2, r3);
                upk2(a2, r4, r5);
                dw[o * 8 + 0] = fmaxf(r0, 0.f);
                dw[o * 8 + 1] = fmaxf(r1, 0.f);
                dw[o * 8 + 2] = fmaxf(r2, 0.f);
                dw[o * 8 + 3] = fmaxf(r3, 0.f);
                dw[o * 8 + 4] = fmaxf(r4, 0.f);
                dw[o * 8 + 5] = fmaxf(r5, 0.f);
                __syncthreads();
            }
        }

        // ---- epilogue: residual + relu, write out ----
        if (active) {
            float r0, r1, r2, r3, r4, r5;
            upk2(a0, r0, r1);
            upk2(a1, r2, r3);
            upk2(a2, r4, r5);
            float* og = out + (size_t)(base + group) * (ND * NP) + o * NP;
            float2 s0, s1, s2;
            s0.x = fmaxf(r0 + d1s[o * 8 + 0], 0.f);
            s0.y = fmaxf(r1 + d1s[o * 8 + 1], 0.f);
            s1.x = fmaxf(r2 + d1s[o * 8 + 2], 0.f);
            s1.y = fmaxf(r3 + d1s[o * 8 + 3], 0.f);
            s2.x = fmaxf(r4 + d1s[o * 8 + 4], 0.f);
            s2.y = fmaxf(r5 + d1s[o * 8 + 5], 0.f);
            *reinterpret_cast<float2*>(og + 0) = s0;
            *reinterpret_cast<float2*>(og + 2) = s1;
            *reinterpret_cast<float2*>(og + 4) = s2;
        }
        __syncthreads();   // protect staging buffers before next tile
    }
}

extern "C" void kernel_launch(void* const* d_in, const int* in_sizes, int n_in,
                              void* d_out, int out_size) {
    const float* x  = (const float*)d_in[0];
    const float* d  = (const float*)d_in[1];
    const float* W1 = (const float*)d_in[2];
    const float* b1 = (const float*)d_in[3];
    const float* W2 = (const float*)d_in[4];
    const float* b2 = (const float*)d_in[5];
    const float* W3 = (const float*)d_in[6];
    const float* b3 = (const float*)d_in[7];
    float* out = (float*)d_out;

    const int n = in_sizes[0] / (ND * 12);

    int sms = 148;
    cudaDeviceGetAttribute(&sms, cudaDevAttrMultiProcessorCount, 0);
    cudaFuncSetAttribute(dijet_resnet_kernel,
                         cudaFuncAttributeMaxDynamicSharedMemorySize, SMEM_BYTES);

    dijet_resnet_kernel<<<sms, THREADS, SMEM_BYTES>>>(x, d, W1, b1, W2, b2, W3, b3,
                                                      out, n);
}

// round 2
// speedup vs baseline: 1.6805x; 1.6805x over previous
#include <cuda_runtime.h>
#include <cstdint>

typedef unsigned long long ull;

#define ND 64
#define NP 6
#define THREADS 512
#define WARPS 16
#define TILE 32                    // samples per block tile (2 per warp)
#define ROWF 20                    // floats per (sample, i) activation row
#define SROWF (ND*ROWF)            // 1280 floats per sample
#define WPAD 65                    // padded o-dim for weight smem
#define WPLANE (ND*WPAD)           // 4160 floats per k-plane
#define ACT_FLOATS (TILE*SROWF)    // 40960
#define W_OFF ACT_FLOATS
#define B_OFF (W_OFF + 3*WPLANE)   // + 12480
#define SMEM_FLOATS (B_OFF + 3*ND)
#define SMEM_BYTES (SMEM_FLOATS*4) // 214528 B < 227 KB

__device__ __forceinline__ ull pk2(float lo, float hi) {
    ull r; asm("mov.b64 %0, {%1,%2};" : "=l"(r) : "f"(lo), "f"(hi)); return r;
}
__device__ __forceinline__ void upk2(ull v, float& lo, float& hi) {
    asm("mov.b64 {%0,%1}, %2;" : "=f"(lo), "=f"(hi) : "l"(v));
}
__device__ __forceinline__ ull ffma2(ull a, ull b, ull c) {
    ull r; asm("fma.rn.f32x2 %0, %1, %2, %3;" : "=l"(r) : "l"(a), "l"(b), "l"(c)); return r;
}

__global__ __launch_bounds__(THREADS, 1)
void dijet_kernel(const float* __restrict__ x, const float* __restrict__ dd,
                  const float* __restrict__ W1, const float* __restrict__ b1,
                  const float* __restrict__ W2, const float* __restrict__ b2,
                  const float* __restrict__ W3, const float* __restrict__ b3,
                  float* __restrict__ out, int n) {
    extern __shared__ float sm[];
    float* acts = sm;              // [32 samples][64 i][20]
    float* Ws   = sm + W_OFF;      // [3 k][64 i][65] (one layer at a time)
    float* Bs   = sm + B_OFF;      // [3][64]

    const int tid = threadIdx.x;
    const int w = tid >> 5, L = tid & 31;

    if (tid < ND) { Bs[tid] = b1[tid]; Bs[ND + tid] = b2[tid]; Bs[2*ND + tid] = b3[tid]; }
    const float* Wg[3] = {W1, W2, W3};

    const int ntiles = (n + TILE - 1) / TILE;
    for (int tile = blockIdx.x; tile < ntiles; tile += gridDim.x) {
        const int base = tile * TILE;
        const int nact = min(TILE, n - base);
        __syncthreads();   // protect act rows from previous tile's compute

        // ---- stage activations: rows [xe01 xo01 d01 xe23 xo23 d23 xe45 xo45 d45 pad2]
        {
            const float2* xg2 = (const float2*)(x + (size_t)base * (ND*12));
            const int limx = nact * (ND*6);
            for (int idx = tid; idx < limx; idx += THREADS) {
                float2 v = xg2[idx];                 // (x[2j], x[2j+1]) = (xe_j, xo_j)
                int s  = idx / (ND*6);
                int rr = idx - s*(ND*6);
                int i  = rr / 6;
                int j  = rr - i*6;
                float* rp = acts + s*SROWF + i*ROWF + (j>>1)*6 + (j&1);
                rp[0] = v.x;          // xe
                rp[2] = v.y;          // xo
            }
            const float2* dg2 = (const float2*)(dd + (size_t)base * (ND*6));
            const int limd = nact * (ND*3);
            for (int idx = tid; idx < limd; idx += THREADS) {
                float2 v = dg2[idx];                 // (d[2j], d[2j+1])
                int s  = idx / (ND*3);
                int rr = idx - s*(ND*3);
                int i  = rr / 3;
                int j  = rr - i*3;
                *(float2*)(acts + s*SROWF + i*ROWF + j*6 + 4) = v;
            }
        }

        float* rs0 = acts + (w*2 + 0) * SROWF;
        float* rs1 = acts + (w*2 + 1) * SROWF;
        ull A[2][2][3];

#pragma unroll
        for (int l = 0; l < 3; ++l) {
            __syncthreads();   // all warps done with previous layer / act staging
            {   // stage this layer's weights: gmem [o][i][k] -> smem [k][i][o+pad]
                const float* Wl = Wg[l];
                for (int idx = tid; idx < ND*ND*3; idx += THREADS) {
                    int o  = idx / 192;
                    int rr = idx - o*192;
                    int i  = rr / 3;
                    int k  = rr - i*3;
                    Ws[k*WPLANE + i*WPAD + o] = Wl[idx];
                }
            }
            __syncthreads();

            {
                float bb0 = Bs[l*ND + L], bb1 = Bs[l*ND + L + 32];
                ull p0 = pk2(bb0, bb0), p1 = pk2(bb1, bb1);
#pragma unroll
                for (int s = 0; s < 2; ++s) {
                    A[s][0][0] = A[s][0][1] = A[s][0][2] = p0;
                    A[s][1][0] = A[s][1][1] = A[s][1][2] = p1;
                }
            }

            const float* wk0 = Ws;
            const float* wk1 = Ws + WPLANE;
            const float* wk2 = Ws + 2*WPLANE;
#pragma unroll 2
            for (int i = 0; i < ND; ++i) {
                const int wi = i*WPAD + L;
                float w00f = wk0[wi], w01f = wk0[wi + 32];
                float w10f = wk1[wi], w11f = wk1[wi + 32];
                float w20f = wk2[wi], w21f = wk2[wi + 32];
                ull wp00 = pk2(w00f, w00f), wp01 = pk2(w01f, w01f);
                ull wp10 = pk2(w10f, w10f), wp11 = pk2(w11f, w11f);
                ull wp20 = pk2(w20f, w20f), wp21 = pk2(w21f, w21f);
#pragma unroll
                for (int s = 0; s < 2; ++s) {
                    const float* rp = (s ? rs1 : rs0) + i*ROWF;
                    ulonglong2 q0 = *(const ulonglong2*)(rp);      // xe01, xo01
                    ulonglong2 q1 = *(const ulonglong2*)(rp + 4);  // d01,  xe23
                    ulonglong2 q2 = *(const ulonglong2*)(rp + 8);  // xo23, d23
                    ulonglong2 q3 = *(const ulonglong2*)(rp + 12); // xe45, xo45
                    ull        q4 = *(const ull*)(rp + 16);        // d45
                    // o-index 0 (o = L)
                    A[s][0][0] = ffma2(q0.x, wp00, A[s][0][0]);
                    A[s][0][0] = ffma2(q0.y, wp10, A[s][0][0]);
                    A[s][0][0] = ffma2(q1.x, wp20, A[s][0][0]);
                    A[s][0][1] = ffma2(q1.y, wp00, A[s][0][1]);
                    A[s][0][1] = ffma2(q2.x, wp10, A[s][0][1]);
                    A[s][0][1] = ffma2(q2.y, wp20, A[s][0][1]);
                    A[s][0][2] = ffma2(q3.x, wp00, A[s][0][2]);
                    A[s][0][2] = ffma2(q3.y, wp10, A[s][0][2]);
                    A[s][0][2] = ffma2(q4,   wp20, A[s][0][2]);
                    // o-index 1 (o = L + 32)
                    A[s][1][0] = ffma2(q0.x, wp01, A[s][1][0]);
                    A[s][1][0] = ffma2(q0.y, wp11, A[s][1][0]);
                    A[s][1][0] = ffma2(q1.x, wp21, A[s][1][0]);
                    A[s][1][1] = ffma2(q1.y, wp01, A[s][1][1]);
                    A[s][1][1] = ffma2(q2.x, wp11, A[s][1][1]);
                    A[s][1][1] = ffma2(q2.y, wp21, A[s][1][1]);
                    A[s][1][2] = ffma2(q3.x, wp01, A[s][1][2]);
                    A[s][1][2] = ffma2(q3.y, wp11, A[s][1][2]);
                    A[s][1][2] = ffma2(q4,   wp21, A[s][1][2]);
                }
            }

            if (l < 2) {
                // relu + write back as next layer's d (input channel = this o)
#pragma unroll
                for (int s = 0; s < 2; ++s) {
                    float* rs = s ? rs1 : rs0;
#pragma unroll
                    for (int oi = 0; oi < 2; ++oi) {
                        int o = L + 32*oi;
                        float* rp = rs + o*ROWF;
                        float v0, v1;
                        upk2(A[s][oi][0], v0, v1);
                        *(float2*)(rp + 4)  = make_float2(fmaxf(v0, 0.f), fmaxf(v1, 0.f));
                        upk2(A[s][oi][1], v0, v1);
                        *(float2*)(rp + 10) = make_float2(fmaxf(v0, 0.f), fmaxf(v1, 0.f));
                        upk2(A[s][oi][2], v0, v1);
                        *(float2*)(rp + 16) = make_float2(fmaxf(v0, 0.f), fmaxf(v1, 0.f));
                    }
                }
            }
        }

        // ---- epilogue: out = relu(layer3 + d1), d1 re-read from gmem
#pragma unroll
        for (int s = 0; s < 2; ++s) {
            int gs = base + w*2 + s;
            if (gs < n) {
#pragma unroll
                for (int oi = 0; oi < 2; ++oi) {
                    int o = L + 32*oi;
                    const float* dg = dd + ((size_t)gs*ND + o)*NP;
                    float*       og = out + ((size_t)gs*ND + o)*NP;
                    float2 e0 = *(const float2*)(dg);
                    float2 e1 = *(const float2*)(dg + 2);
                    float2 e2 = *(const float2*)(dg + 4);
                    float v0, v1;
                    upk2(A[s][oi][0], v0, v1);
                    *(float2*)(og)     = make_float2(fmaxf(v0 + e0.x, 0.f), fmaxf(v1 + e0.y, 0.f));
                    upk2(A[s][oi][1], v0, v1);
                    *(float2*)(og + 2) = make_float2(fmaxf(v0 + e1.x, 0.f), fmaxf(v1 + e1.y, 0.f));
                    upk2(A[s][oi][2], v0, v1);
                    *(float2*)(og + 4) = make_float2(fmaxf(v0 + e2.x, 0.f), fmaxf(v1 + e2.y, 0.f));
                }
            }
        }
    }
}

extern "C" void kernel_launch(void* const* d_in, const int* in_sizes, int n_in,
                              void* d_out, int out_size) {
    const float* x  = (const float*)d_in[0];
    const float* dd = (const float*)d_in[1];
    const float* W1 = (const float*)d_in[2];
    const float* b1 = (const float*)d_in[3];
    const float* W2 = (const float*)d_in[4];
    const float* b2 = (const float*)d_in[5];
    const float* W3 = (const float*)d_in[6];
    const float* b3 = (const float*)d_in[7];
    float* out = (float*)d_out;

    const int n = in_sizes[0] / (ND * 12);

    int sms = 148;
    cudaDeviceGetAttribute(&sms, cudaDevAttrMultiProcessorCount, 0);
    cudaFuncSetAttribute(dijet_kernel,
                         cudaFuncAttributeMaxDynamicSharedMemorySize, SMEM_BYTES);

    dijet_kernel<<<sms, THREADS, SMEM_BYTES>>>(x, dd, W1, b1, W2, b2, W3, b3, out, n);
}

// round 3
// speedup vs baseline: 1.6810x; 1.0003x over previous
#include <cuda_runtime.h>
#include <cstdint>

typedef unsigned long long ull;

#define ND 64
#define NP 6
#define THREADS 512
#define WARPS 16
#define TILE 32                    // samples per block tile (2 per warp)
#define ROWF 20                    // floats per (sample, i) activation row
#define SROWF (ND*ROWF)            // 1280 floats per sample
#define WPAD 65                    // padded o-dim for weight smem
#define WPLANE (ND*WPAD)           // 4160 floats per k-plane
#define ACT_FLOATS (TILE*SROWF)    // 40960
#define W_OFF ACT_FLOATS
#define B_OFF (W_OFF + 3*WPLANE)   // + 12480
#define SMEM_FLOATS (B_OFF + 3*ND)
#define SMEM_BYTES (SMEM_FLOATS*4) // 214528 B < 227 KB

__device__ __forceinline__ ull pk2(float lo, float hi) {
    ull r; asm("mov.b64 %0, {%1,%2};" : "=l"(r) : "f"(lo), "f"(hi)); return r;
}
__device__ __forceinline__ void upk2(ull v, float& lo, float& hi) {
    asm("mov.b64 {%0,%1}, %2;" : "=f"(lo), "=f"(hi) : "l"(v));
}
__device__ __forceinline__ ull ffma2(ull a, ull b, ull c) {
    ull r; asm("fma.rn.f32x2 %0, %1, %2, %3;" : "=l"(r) : "l"(a), "l"(b), "l"(c)); return r;
}

__global__ __launch_bounds__(THREADS, 1)
void dijet_kernel(const float* __restrict__ x, const float* __restrict__ dd,
                  const float* __restrict__ W1, const float* __restrict__ b1,
                  const float* __restrict__ W2, const float* __restrict__ b2,
                  const float* __restrict__ W3, const float* __restrict__ b3,
                  float* __restrict__ out, int n) {
    extern __shared__ float sm[];
    float* acts = sm;              // [32 samples][64 i][20]
    float* Ws   = sm + W_OFF;      // [3 k][64 i][65] (one layer at a time)
    float* Bs   = sm + B_OFF;      // [3][64]

    const int tid = threadIdx.x;
    const int w = tid >> 5, L = tid & 31;

    if (tid < ND) { Bs[tid] = b1[tid]; Bs[ND + tid] = b2[tid]; Bs[2*ND + tid] = b3[tid]; }
    const float* Wg[3] = {W1, W2, W3};

    const int ntiles = (n + TILE - 1) / TILE;
    for (int tile = blockIdx.x; tile < ntiles; tile += gridDim.x) {
        const int base = tile * TILE;
        const int nact = min(TILE, n - base);
        __syncthreads();   // protect act rows from previous tile's compute

        // ---- stage activations: rows [xe01 xo01 d01 xe23 xo23 d23 xe45 xo45 d45 pad2]
        {
            const float2* xg2 = (const float2*)(x + (size_t)base * (ND*12));
            const int limx = nact * (ND*6);
            for (int idx = tid; idx < limx; idx += THREADS) {
                float2 v = xg2[idx];                 // (x[2j], x[2j+1]) = (xe_j, xo_j)
                int s  = idx / (ND*6);
                int rr = idx - s*(ND*6);
                int i  = rr / 6;
                int j  = rr - i*6;
                float* rp = acts + s*SROWF + i*ROWF + (j>>1)*6 + (j&1);
                rp[0] = v.x;          // xe
                rp[2] = v.y;          // xo
            }
            const float2* dg2 = (const float2*)(dd + (size_t)base * (ND*6));
            const int limd = nact * (ND*3);
            for (int idx = tid; idx < limd; idx += THREADS) {
                float2 v = dg2[idx];                 // (d[2j], d[2j+1])
                int s  = idx / (ND*3);
                int rr = idx - s*(ND*3);
                int i  = rr / 3;
                int j  = rr - i*3;
                *(float2*)(acts + s*SROWF + i*ROWF + j*6 + 4) = v;
            }
        }

        float* rs0 = acts + (w*2 + 0) * SROWF;
        float* rs1 = acts + (w*2 + 1) * SROWF;
        ull A[2][2][3];

#pragma unroll
        for (int l = 0; l < 3; ++l) {
            __syncthreads();   // all warps done with previous layer / act staging
            {   // stage this layer's weights: gmem [o][i][k] -> smem [k][i][o+pad]
                const float* Wl = Wg[l];
                for (int idx = tid; idx < ND*ND*3; idx += THREADS) {
                    int o  = idx / 192;
                    int rr = idx - o*192;
                    int i  = rr / 3;
                    int k  = rr - i*3;
                    Ws[k*WPLANE + i*WPAD + o] = Wl[idx];
                }
            }
            __syncthreads();

            {
                float bb0 = Bs[l*ND + L], bb1 = Bs[l*ND + L + 32];
                ull p0 = pk2(bb0, bb0), p1 = pk2(bb1, bb1);
#pragma unroll
                for (int s = 0; s < 2; ++s) {
                    A[s][0][0] = A[s][0][1] = A[s][0][2] = p0;
                    A[s][1][0] = A[s][1][1] = A[s][1][2] = p1;
                }
            }

            const float* wk0 = Ws;
            const float* wk1 = Ws + WPLANE;
            const float* wk2 = Ws + 2*WPLANE;
#pragma unroll 2
            for (int i = 0; i < ND; ++i) {
                const int wi = i*WPAD + L;
                float w00f = wk0[wi], w01f = wk0[wi + 32];
                float w10f = wk1[wi], w11f = wk1[wi + 32];
                float w20f = wk2[wi], w21f = wk2[wi + 32];
                ull wp00 = pk2(w00f, w00f), wp01 = pk2(w01f, w01f);
                ull wp10 = pk2(w10f, w10f), wp11 = pk2(w11f, w11f);
                ull wp20 = pk2(w20f, w20f), wp21 = pk2(w21f, w21f);
#pragma unroll
                for (int s = 0; s < 2; ++s) {
                    const float* rp = (s ? rs1 : rs0) + i*ROWF;
                    ulonglong2 q0 = *(const ulonglong2*)(rp);      // xe01, xo01
                    ulonglong2 q1 = *(const ulonglong2*)(rp + 4);  // d01,  xe23
                    ulonglong2 q2 = *(const ulonglong2*)(rp + 8);  // xo23, d23
                    ulonglong2 q3 = *(const ulonglong2*)(rp + 12); // xe45, xo45
                    ull        q4 = *(const ull*)(rp + 16);        // d45
                    // o-index 0 (o = L)
                    A[s][0][0] = ffma2(q0.x, wp00, A[s][0][0]);
                    A[s][0][0] = ffma2(q0.y, wp10, A[s][0][0]);
                    A[s][0][0] = ffma2(q1.x, wp20, A[s][0][0]);
                    A[s][0][1] = ffma2(q1.y, wp00, A[s][0][1]);
                    A[s][0][1] = ffma2(q2.x, wp10, A[s][0][1]);
                    A[s][0][1] = ffma2(q2.y, wp20, A[s][0][1]);
                    A[s][0][2] = ffma2(q3.x, wp00, A[s][0][2]);
                    A[s][0][2] = ffma2(q3.y, wp10, A[s][0][2]);
                    A[s][0][2] = ffma2(q4,   wp20, A[s][0][2]);
                    // o-index 1 (o = L + 32)
                    A[s][1][0] = ffma2(q0.x, wp01, A[s][1][0]);
                    A[s][1][0] = ffma2(q0.y, wp11, A[s][1][0]);
                    A[s][1][0] = ffma2(q1.x, wp21, A[s][1][0]);
                    A[s][1][1] = ffma2(q1.y, wp01, A[s][1][1]);
                    A[s][1][1] = ffma2(q2.x, wp11, A[s][1][1]);
                    A[s][1][1] = ffma2(q2.y, wp21, A[s][1][1]);
                    A[s][1][2] = ffma2(q3.x, wp01, A[s][1][2]);
                    A[s][1][2] = ffma2(q3.y, wp11, A[s][1][2]);
                    A[s][1][2] = ffma2(q4,   wp21, A[s][1][2]);
                }
            }

            if (l < 2) {
                // relu + write back as next layer's d (input channel = this o)
#pragma unroll
                for (int s = 0; s < 2; ++s) {
                    float* rs = s ? rs1 : rs0;
#pragma unroll
                    for (int oi = 0; oi < 2; ++oi) {
                        int o = L + 32*oi;
                        float* rp = rs + o*ROWF;
                        float v0, v1;
                        upk2(A[s][oi][0], v0, v1);
                        *(float2*)(rp + 4)  = make_float2(fmaxf(v0, 0.f), fmaxf(v1, 0.f));
                        upk2(A[s][oi][1], v0, v1);
                        *(float2*)(rp + 10) = make_float2(fmaxf(v0, 0.f), fmaxf(v1, 0.f));
                        upk2(A[s][oi][2], v0, v1);
                        *(float2*)(rp + 16) = make_float2(fmaxf(v0, 0.f), fmaxf(v1, 0.f));
                    }
                }
            }
        }

        // ---- epilogue: out = relu(layer3 + d1), d1 re-read from gmem
#pragma unroll
        for (int s = 0; s < 2; ++s) {
            int gs = base + w*2 + s;
            if (gs < n) {
#pragma unroll
                for (int oi = 0; oi < 2; ++oi) {
                    int o = L + 32*oi;
                    const float* dg = dd + ((size_t)gs*ND + o)*NP;
                    float*       og = out + ((size_t)gs*ND + o)*NP;
                    float2 e0 = *(const float2*)(dg);
                    float2 e1 = *(const float2*)(dg + 2);
                    float2 e2 = *(const float2*)(dg + 4);
                    float v0, v1;
                    upk2(A[s][oi][0], v0, v1);
                    *(float2*)(og)     = make_float2(fmaxf(v0 + e0.x, 0.f), fmaxf(v1 + e0.y, 0.f));
                    upk2(A[s][oi][1], v0, v1);
                    *(float2*)(og + 2) = make_float2(fmaxf(v0 + e1.x, 0.f), fmaxf(v1 + e1.y, 0.f));
                    upk2(A[s][oi][2], v0, v1);
                    *(float2*)(og + 4) = make_float2(fmaxf(v0 + e2.x, 0.f), fmaxf(v1 + e2.y, 0.f));
                }
            }
        }
    }
}

extern "C" void kernel_launch(void* const* d_in, const int* in_sizes, int n_in,
                              void* d_out, int out_size) {
    const float* x  = (const float*)d_in[0];
    const float* dd = (const float*)d_in[1];
    const float* W1 = (const float*)d_in[2];
    const float* b1 = (const float*)d_in[3];
    const float* W2 = (const float*)d_in[4];
    const float* b2 = (const float*)d_in[5];
    const float* W3 = (const float*)d_in[6];
    const float* b3 = (const float*)d_in[7];
    float* out = (float*)d_out;

    const int n = in_sizes[0] / (ND * 12);

    int sms = 148;
    cudaDeviceGetAttribute(&sms, cudaDevAttrMultiProcessorCount, 0);
    cudaFuncSetAttribute(dijet_kernel,
                         cudaFuncAttributeMaxDynamicSharedMemorySize, SMEM_BYTES);

    dijet_kernel<<<sms, THREADS, SMEM_BYTES>>>(x, dd, W1, b1, W2, b2, W3, b3, out, n);
}

// round 5
// speedup vs baseline: 3.6605x; 2.1775x over previous
#include <cuda_runtime.h>
#include <cuda_bf16.h>
#include <cstdint>

#define ND 64
#define THREADS 384
#define TILE_S 32            // samples per CTA tile (192 rows)
#define CH_S 16              // samples per staging chunk (96 rows = 6 warps)

// ---- smem layout (bytes) ----
#define BF_OFF   0                    // uint4 [6 lv][12 j][4 p][32 lane] = 147456
#define BIAS_OFF 147456               // 192 floats
#define SCR_OFF  148224               // 12288 floats = 49152 B
#define SMEM_BYTES (148224 + 49152)   // 197376

// fp32 -> (bf16 hi, bf16 lo) packed words; low half = first element
__device__ __forceinline__ void split_pk(float v0, float v1, uint32_t& hw, uint32_t& lw) {
    __nv_bfloat16 h0 = __float2bfloat16(v0), h1 = __float2bfloat16(v1);
    __nv_bfloat16 l0 = __float2bfloat16(v0 - __bfloat162float(h0));
    __nv_bfloat16 l1 = __float2bfloat16(v1 - __bfloat162float(h1));
    hw = (uint32_t)__bfloat16_as_ushort(h0) | ((uint32_t)__bfloat16_as_ushort(h1) << 16);
    lw = (uint32_t)__bfloat16_as_ushort(l0) | ((uint32_t)__bfloat16_as_ushort(l1) << 16);
}

__device__ __forceinline__ void mma4(float* c, const uint32_t* a, uint32_t b0, uint32_t b1) {
    asm volatile(
        "mma.sync.aligned.m16n8k16.row.col.f32.bf16.bf16.f32 "
        "{%0,%1,%2,%3}, {%4,%5,%6,%7}, {%8,%9}, {%0,%1,%2,%3};"
        : "+f"(c[0]), "+f"(c[1]), "+f"(c[2]), "+f"(c[3])
        : "r"(a[0]), "r"(a[1]), "r"(a[2]), "r"(a[3]), "r"(b0), "r"(b1));
}

__global__ __launch_bounds__(THREADS, 1)
void dijet_mma(const float* __restrict__ x, const float* __restrict__ dd,
               const float* __restrict__ W1, const float* __restrict__ b1,
               const float* __restrict__ W2, const float* __restrict__ b2,
               const float* __restrict__ W3, const float* __restrict__ b3,
               float* __restrict__ out, int n) {
    extern __shared__ char smem[];
    uint4*  Bfr  = (uint4*)(smem + BF_OFF);
    float*  bias = (float*)(smem + BIAS_OFF);
    float*  scr  = (float*)(smem + SCR_OFF);

    const int tid  = threadIdx.x;
    const int w    = tid >> 5;
    const int lane = tid & 31;
    const int g    = lane >> 2;     // row-in-frag 0..7
    const int c    = lane & 3;      // k/n sub-index

    if (tid < 64) { bias[tid] = b1[tid]; bias[64 + tid] = b2[tid]; bias[128 + tid] = b3[tid]; }

    // ==== stage weights once: fp32 [o][i][k] -> bf16 hi/lo fragments ====
    {
        const float* Wg[3] = {W1, W2, W3};
        for (int l = 0; l < 3; ++l) {
            for (int oh = 0; oh < 2; ++oh) {
                __syncthreads();
                const float4* src = (const float4*)(Wg[l] + oh * 32 * 192);
                float4* dst = (float4*)scr;
                for (int i4 = tid; i4 < 1536; i4 += THREADS) dst[i4] = src[i4];
                __syncthreads();
#pragma unroll
                for (int q = 0; q < 2; ++q) {
                    int cmb = w * 2 + q;            // 0..23
                    int j = cmb >> 1, pp = cmb & 1, p = oh * 2 + pp;
                    int nl0 = pp * 16 + g, nl1 = nl0 + 8;
                    int k0 = j * 16 + 2 * c;
                    int blk = k0 >> 6, i0 = k0 & 63;
                    const float* s0p = scr + nl0 * 192 + blk;
                    const float* s1p = scr + nl1 * 192 + blk;
                    uint32_t h0, l0, h1, l1, h2, l2, h3, l3;
                    split_pk(s0p[i0 * 3],       s0p[(i0 + 1) * 3], h0, l0);
                    split_pk(s0p[(i0 + 8) * 3], s0p[(i0 + 9) * 3], h1, l1);
                    split_pk(s1p[i0 * 3],       s1p[(i0 + 1) * 3], h2, l2);
                    split_pk(s1p[(i0 + 8) * 3], s1p[(i0 + 9) * 3], h3, l3);
                    Bfr[(((l * 2 + 0) * 12 + j) * 4 + p) * 32 + lane] = make_uint4(h0, h1, h2, h3);
                    Bfr[(((l * 2 + 1) * 12 + j) * 4 + p) * 32 + lane] = make_uint4(l0, l1, l2, l3);
                }
            }
        }
    }

    const int ntiles = (n + TILE_S - 1) / TILE_S;
    for (int tile = blockIdx.x; tile < ntiles; tile += gridDim.x) {
        const int s0 = tile * TILE_S;

        uint32_t Ahx[8][4], Alx[8][4], Ahd[4][4], Ald[4][4];

        // ==== stage + fill x fragments (2 chunks of 16 samples) ====
        for (int ch = 0; ch < 2; ++ch) {
            __syncthreads();
            const int cs = s0 + ch * CH_S;
            const int csn = min(CH_S, max(0, n - cs));
            {
                const float4* src = (const float4*)(x + (size_t)cs * 768);
                float4* dst = (float4*)scr;
                const int cnt4 = csn * 192;
                for (int i4 = tid; i4 < cnt4; i4 += THREADS) dst[i4] = src[i4];
            }
            __syncthreads();
            if ((w / 6) == ch) {
                const int clr = (w - ch * 6) * 16 + g;     // chunk-local row
                const int sl  = clr / 6,  slot  = clr - sl * 6;
                const int clr2 = clr + 8;
                const int sl2 = clr2 / 6, slot2 = clr2 - sl2 * 6;
                const bool v0 = sl < csn, v1 = sl2 < csn;
                const float* r0p = scr + sl  * 768 + 2 * slot;
                const float* r1p = scr + sl2 * 768 + 2 * slot2;
#pragma unroll
                for (int j = 0; j < 8; ++j) {
                    const int blk = j >> 2;
                    const int i0 = (j & 3) * 16 + 2 * c;
                    const float* q0 = r0p + blk;
                    const float* q1 = r1p + blk;
                    float e00 = v0 ? q0[i0 * 12]       : 0.f;
                    float e01 = v0 ? q0[(i0 + 1) * 12] : 0.f;
                    float e02 = v0 ? q0[(i0 + 8) * 12] : 0.f;
                    float e03 = v0 ? q0[(i0 + 9) * 12] : 0.f;
                    float e10 = v1 ? q1[i0 * 12]       : 0.f;
                    float e11 = v1 ? q1[(i0 + 1) * 12] : 0.f;
                    float e12 = v1 ? q1[(i0 + 8) * 12] : 0.f;
                    float e13 = v1 ? q1[(i0 + 9) * 12] : 0.f;
                    split_pk(e00, e01, Ahx[j][0], Alx[j][0]);
                    split_pk(e10, e11, Ahx[j][1], Alx[j][1]);
                    split_pk(e02, e03, Ahx[j][2], Alx[j][2]);
                    split_pk(e12, e13, Ahx[j][3], Alx[j][3]);
                }
            }
        }
        // ==== stage + fill layer-1 d fragments ====
        for (int ch = 0; ch < 2; ++ch) {
            __syncthreads();
            const int cs = s0 + ch * CH_S;
            const int csn = min(CH_S, max(0, n - cs));
            {
                const float4* src = (const float4*)(dd + (size_t)cs * 384);
                float4* dst = (float4*)scr;
                const int cnt4 = csn * 96;
                for (int i4 = tid; i4 < cnt4; i4 += THREADS) dst[i4] = src[i4];
            }
            __syncthreads();
            if ((w / 6) == ch) {
                const int clr = (w - ch * 6) * 16 + g;
                const int sl  = clr / 6,  slot  = clr - sl * 6;
                const int clr2 = clr + 8;
                const int sl2 = clr2 / 6, slot2 = clr2 - sl2 * 6;
                const bool v0 = sl < csn, v1 = sl2 < csn;
                const float* r0p = scr + sl  * 384 + slot;
                const float* r1p = scr + sl2 * 384 + slot2;
#pragma unroll
                for (int jd = 0; jd < 4; ++jd) {
                    const int i0 = jd * 16 + 2 * c;
                    float e00 = v0 ? r0p[i0 * 6]       : 0.f;
                    float e01 = v0 ? r0p[(i0 + 1) * 6] : 0.f;
                    float e02 = v0 ? r0p[(i0 + 8) * 6] : 0.f;
                    float e03 = v0 ? r0p[(i0 + 9) * 6] : 0.f;
                    float e10 = v1 ? r1p[i0 * 6]       : 0.f;
                    float e11 = v1 ? r1p[(i0 + 1) * 6] : 0.f;
                    float e12 = v1 ? r1p[(i0 + 8) * 6] : 0.f;
                    float e13 = v1 ? r1p[(i0 + 9) * 6] : 0.f;
                    split_pk(e00, e01, Ahd[jd][0], Ald[jd][0]);
                    split_pk(e10, e11, Ahd[jd][1], Ald[jd][1]);
                    split_pk(e02, e03, Ahd[jd][2], Ald[jd][2]);
                    split_pk(e12, e13, Ahd[jd][3], Ald[jd][3]);
                }
            }
        }

        float acc[8][4];
#pragma unroll
        for (int nt = 0; nt < 8; ++nt)
#pragma unroll
            for (int e = 0; e < 4; ++e) acc[nt][e] = 0.f;

        // ==== 3 chained layers ====
#pragma unroll
        for (int l = 0; l < 3; ++l) {
#pragma unroll
            for (int j = 0; j < 12; ++j) {
                const uint32_t* Ah = (j < 8) ? Ahx[j] : Ahd[j - 8];
                const uint32_t* Al = (j < 8) ? Alx[j] : Ald[j - 8];
                const uint4* bhp = Bfr + (((l * 2 + 0) * 12 + j) * 4) * 32 + lane;
                const uint4* blp = Bfr + (((l * 2 + 1) * 12 + j) * 4) * 32 + lane;
#pragma unroll
                for (int p = 0; p < 4; ++p) {
                    uint4 bh = bhp[p * 32];
                    uint4 bl = blp[p * 32];
                    mma4(acc[2 * p],     Ah, bh.x, bh.y);
                    mma4(acc[2 * p],     Ah, bl.x, bl.y);
                    mma4(acc[2 * p],     Al, bh.x, bh.y);
                    mma4(acc[2 * p + 1], Ah, bh.z, bh.w);
                    mma4(acc[2 * p + 1], Ah, bl.z, bl.w);
                    mma4(acc[2 * p + 1], Al, bh.z, bh.w);
                }
            }
            if (l < 2) {
                // D -> next-layer d fragments, register-local (o dim == next k dim)
#pragma unroll
                for (int jd = 0; jd < 4; ++jd) {
                    const int o0 = jd * 16 + 2 * c;
                    float bb0 = bias[l * 64 + o0],     bb1 = bias[l * 64 + o0 + 1];
                    float bb8 = bias[l * 64 + o0 + 8], bb9 = bias[l * 64 + o0 + 9];
                    float t0 = fmaxf(acc[2 * jd][0] + bb0, 0.f);
                    float t1 = fmaxf(acc[2 * jd][1] + bb1, 0.f);
                    float t2 = fmaxf(acc[2 * jd][2] + bb0, 0.f);
                    float t3 = fmaxf(acc[2 * jd][3] + bb1, 0.f);
                    float u0 = fmaxf(acc[2 * jd + 1][0] + bb8, 0.f);
                    float u1 = fmaxf(acc[2 * jd + 1][1] + bb9, 0.f);
                    float u2 = fmaxf(acc[2 * jd + 1][2] + bb8, 0.f);
                    float u3 = fmaxf(acc[2 * jd + 1][3] + bb9, 0.f);
                    split_pk(t0, t1, Ahd[jd][0], Ald[jd][0]);
                    split_pk(t2, t3, Ahd[jd][1], Ald[jd][1]);
                    split_pk(u0, u1, Ahd[jd][2], Ald[jd][2]);
                    split_pk(u2, u3, Ahd[jd][3], Ald[jd][3]);
#pragma unroll
                    for (int e = 0; e < 4; ++e) {
                        acc[2 * jd][e] = 0.f;
                        acc[2 * jd + 1][e] = 0.f;
                    }
                }
            }
        }

        // ==== final epilogue: relu(D + b3 + d1) -> gmem ====
        {
            const long rmax = (long)n * 6;
            const long r0 = (long)s0 * 6 + w * 16 + g;
            const long r1 = r0 + 8;
            const bool v0 = r0 < rmax, v1 = r1 < rmax;
            const int  sa0 = (int)(r0 / 6), sl0 = (int)(r0 - (long)sa0 * 6);
            const int  sa1 = (int)(r1 / 6), sl1 = (int)(r1 - (long)sa1 * 6);
            const size_t base0 = (size_t)sa0 * 384 + sl0;
            const size_t base1 = (size_t)sa1 * 384 + sl1;
#pragma unroll
            for (int nt = 0; nt < 8; ++nt) {
                const int o0 = nt * 8 + 2 * c;
                const float bb0 = bias[128 + o0], bb1 = bias[128 + o0 + 1];
                if (v0) {
                    size_t a00 = base0 + (size_t)o0 * 6, a01 = a00 + 6;
                    out[a00] = fmaxf(acc[nt][0] + bb0 + dd[a00], 0.f);
                    out[a01] = fmaxf(acc[nt][1] + bb1 + dd[a01], 0.f);
                }
                if (v1) {
                    size_t a10 = base1 + (size_t)o0 * 6, a11 = a10 + 6;
                    out[a10] = fmaxf(acc[nt][2] + bb0 + dd[a10], 0.f);
                    out[a11] = fmaxf(acc[nt][3] + bb1 + dd[a11], 0.f);
                }
            }
        }
    }
}

extern "C" void kernel_launch(void* const* d_in, const int* in_sizes, int n_in,
                              void* d_out, int out_size) {
    const float* x  = (const float*)d_in[0];
    const float* dd = (const float*)d_in[1];
    const float* W1 = (const float*)d_in[2];
    const float* b1 = (const float*)d_in[3];
    const float* W2 = (const float*)d_in[4];
    const float* b2 = (const float*)d_in[5];
    const float* W3 = (const float*)d_in[6];
    const float* b3 = (const float*)d_in[7];
    float* out = (float*)d_out;

    const int n = in_sizes[0] / (ND * 12);

    int sms = 148;
    cudaDeviceGetAttribute(&sms, cudaDevAttrMultiProcessorCount, 0);
    cudaFuncSetAttribute(dijet_mma, cudaFuncAttributeMaxDynamicSharedMemorySize, SMEM_BYTES);

    dijet_mma<<<sms, THREADS, SMEM_BYTES>>>(x, dd, W1, b1, W2, b2, W3, b3, out, n);
}